// round 14
// baseline (speedup 1.0000x reference)
#include <cuda_runtime.h>
#include <cstdint>

#define NN     100000
#define EE     1000000
#define DIN    128
#define DOUT   64
#define DEDGE  11
#define ET     (EE + NN)
#define FULL   0xFFFFFFFFu

// ---------------- scratch (device globals) ----------------------------------
__device__ float g_xl[NN * DOUT];          // x @ W_l   (25.6 MB)
__device__ float g_xr[NN * DOUT];          // x @ W_r   (25.6 MB)
__device__ int   g_cnt[NN];                // in-degree
__device__ int   g_off[NN];                // CSR offsets (exclusive scan)
__device__ int   g_cur[NN];                // fill cursors
__device__ int2  g_csr[EE];                // (edge_id, src) grouped by dst

// ---------------- 0: zero counters ------------------------------------------
__global__ void k_zero() {
    int i = blockIdx.x * blockDim.x + threadIdx.x;
    if (i < NN) g_cnt[i] = 0;
}

// ---------------- 1: in-degree histogram -------------------------------------
__global__ void k_count(const int* __restrict__ ei) {
    int e = blockIdx.x * blockDim.x + threadIdx.x;
    if (e >= EE) return;
    atomicAdd(&g_cnt[__ldg(&ei[EE + e])], 1);
}

// ---------------- 2: exclusive prefix scan (single block) --------------------
__global__ void k_scan() {
    __shared__ int warp_sums[32];
    __shared__ int s_carry, s_total;
    int tid = threadIdx.x;
    int lane = tid & 31, wid = tid >> 5;
    if (tid == 0) s_carry = 0;
    __syncthreads();
    for (int base = 0; base < NN; base += 1024) {
        int i = base + tid;
        int v = (i < NN) ? g_cnt[i] : 0;
        int incl = v;
#pragma unroll
        for (int o = 1; o < 32; o <<= 1) {
            int t = __shfl_up_sync(FULL, incl, o);
            if (lane >= o) incl += t;
        }
        if (lane == 31) warp_sums[wid] = incl;
        __syncthreads();
        if (wid == 0) {
            int ws = warp_sums[lane];
            int wincl = ws;
#pragma unroll
            for (int o = 1; o < 32; o <<= 1) {
                int t = __shfl_up_sync(FULL, wincl, o);
                if (lane >= o) wincl += t;
            }
            warp_sums[lane] = wincl - ws;       // exclusive warp offset
            if (lane == 31) s_total = wincl;    // chunk total
        }
        __syncthreads();
        int excl = incl - v + warp_sums[wid] + s_carry;
        if (i < NN) { g_off[i] = excl; g_cur[i] = excl; }
        __syncthreads();
        if (tid == 0) s_carry += s_total;
        __syncthreads();
    }
}

// ---------------- 3: CSR fill -------------------------------------------------
__global__ void k_fill(const int* __restrict__ ei) {
    int e = blockIdx.x * blockDim.x + threadIdx.x;
    if (e >= EE) return;
    int src = __ldg(&ei[e]);
    int dst = __ldg(&ei[EE + e]);
    int pos = atomicAdd(&g_cur[dst], 1);
    g_csr[pos] = make_int2(e, src);
}

// ---------------- 4: tensor-core GEMM (3xTF32), W pre-split in smem ----------
#define SXS   132
#define SWS   72
#define SM_X    0
#define SM_WH  (SM_X + 64 * SXS)            // 8448
#define SM_WLO (SM_WH + 128 * SWS)          // 17664
#define SM_TOT_F (SM_WLO + 128 * SWS)       // 26880 floats = 107520 B
#define TILE_M 64

__device__ __forceinline__ unsigned f2tf(float f) {
    unsigned u;
    asm("cvt.rna.tf32.f32 %0, %1;" : "=r"(u) : "f"(f));
    return u;
}
__device__ __forceinline__ void mma_tf32(float* d, unsigned a0, unsigned a1,
                                         unsigned a2, unsigned a3,
                                         unsigned b0, unsigned b1) {
    asm volatile(
        "mma.sync.aligned.m16n8k8.row.col.f32.tf32.tf32.f32 "
        "{%0,%1,%2,%3}, {%4,%5,%6,%7}, {%8,%9}, {%0,%1,%2,%3};"
        : "+f"(d[0]), "+f"(d[1]), "+f"(d[2]), "+f"(d[3])
        : "r"(a0), "r"(a1), "r"(a2), "r"(a3), "r"(b0), "r"(b1));
}

__global__ void __launch_bounds__(256, 2)
k_gemm(const float* __restrict__ x, const float* __restrict__ W, int is_l) {
    extern __shared__ float sm[];
    float* sx = sm + SM_X;
    float* gout = is_l ? g_xl : g_xr;   // device-side symbol reference (valid)

    int tid  = threadIdx.x;
    int warp = tid >> 5;
    int lane = tid & 31;
    int grp  = lane >> 2;
    int ctid = lane & 3;

    // --- fill W as tf32 hi/lo (once per block, float4-wide) ---
    for (int i = tid; i < (DIN * DOUT) / 4; i += 256) {
        int k = i >> 4, n4 = (i & 15) * 4;
        float4 v = __ldg((const float4*)W + i);
        float4 hi, lo;
        hi.x = __uint_as_float(f2tf(v.x)); lo.x = __uint_as_float(f2tf(v.x - hi.x));
        hi.y = __uint_as_float(f2tf(v.y)); lo.y = __uint_as_float(f2tf(v.y - hi.y));
        hi.z = __uint_as_float(f2tf(v.z)); lo.z = __uint_as_float(f2tf(v.z - hi.z));
        hi.w = __uint_as_float(f2tf(v.w)); lo.w = __uint_as_float(f2tf(v.w - hi.w));
        *(float4*)&sm[SM_WH  + k * SWS + n4] = hi;
        *(float4*)&sm[SM_WLO + k * SWS + n4] = lo;
    }

    // --- load x tile 64 x 128 (zero-pad OOB rows) ---
    int row0 = blockIdx.x * TILE_M;
    {
        const float4* xg = (const float4*)x;
        for (int i = tid; i < TILE_M * 32; i += 256) {
            int r = i >> 5, c4 = i & 31;
            float4 v = make_float4(0.f, 0.f, 0.f, 0.f);
            if (row0 + r < NN) v = xg[(size_t)(row0 + r) * 32 + c4];
            *(float4*)&sx[r * SXS + c4 * 4] = v;
        }
    }
    __syncthreads();

    int rb = (warp & 3) * 16;      // row slab within tile
    int nh = (warp >> 2) * 32;     // n-half base column

    float d[4][4];
#pragma unroll
    for (int t = 0; t < 4; t++)
#pragma unroll
        for (int q = 0; q < 4; q++) d[t][q] = 0.f;

#pragma unroll 1
    for (int k0 = 0; k0 < DIN; k0 += 8) {
        // B fragments: pure LDS, already tf32
        unsigned bh[4][2], bl[4][2];
        const float* ph0 = sm + SM_WH  + (k0 + ctid) * SWS + nh + grp;
        const float* ph1 = sm + SM_WH  + (k0 + ctid + 4) * SWS + nh + grp;
        const float* pl0 = sm + SM_WLO + (k0 + ctid) * SWS + nh + grp;
        const float* pl1 = sm + SM_WLO + (k0 + ctid + 4) * SWS + nh + grp;
#pragma unroll
        for (int t = 0; t < 4; t++) {
            bh[t][0] = __float_as_uint(ph0[8 * t]);
            bh[t][1] = __float_as_uint(ph1[8 * t]);
            bl[t][0] = __float_as_uint(pl0[8 * t]);
            bl[t][1] = __float_as_uint(pl1[8 * t]);
        }
        // A fragment: cvt on the fly (only 4 values)
        float f0 = sx[(rb + grp)     * SXS + k0 + ctid];
        float f1 = sx[(rb + grp + 8) * SXS + k0 + ctid];
        float f2 = sx[(rb + grp)     * SXS + k0 + ctid + 4];
        float f3 = sx[(rb + grp + 8) * SXS + k0 + ctid + 4];
        unsigned a0 = f2tf(f0), a1 = f2tf(f1), a2 = f2tf(f2), a3 = f2tf(f3);
        unsigned l0 = f2tf(f0 - __uint_as_float(a0));
        unsigned l1 = f2tf(f1 - __uint_as_float(a1));
        unsigned l2 = f2tf(f2 - __uint_as_float(a2));
        unsigned l3 = f2tf(f3 - __uint_as_float(a3));
#pragma unroll
        for (int t = 0; t < 4; t++) {
            mma_tf32(d[t], a0, a1, a2, a3, bh[t][0], bh[t][1]);
            mma_tf32(d[t], l0, l1, l2, l3, bh[t][0], bh[t][1]);
            mma_tf32(d[t], a0, a1, a2, a3, bl[t][0], bl[t][1]);
        }
    }

    {
        int r0 = row0 + rb + grp;
        int r1 = r0 + 8;
#pragma unroll
        for (int t = 0; t < 4; t++) {
            int col = nh + 8 * t + 2 * ctid;
            if (r0 < NN)
                *(float2*)&gout[(size_t)r0 * DOUT + col] =
                    make_float2(d[t][0], d[t][1]);
            if (r1 < NN)
                *(float2*)&gout[(size_t)r1 * DOUT + col] =
                    make_float2(d[t][2], d[t][3]);
        }
    }
}

// ---------------- 5: CSR aggregation: half-warp per edge ---------------------
// One warp per destination; lane = h*16+c. Lane owns dims [4c, 4c+4).
// Half h processes edge j+h -> each width-16 shfl serves TWO edges.
// MIO ops/edge: 5.5 broadcast shfls + 2 butterfly shfls. We in registers.
// Invalid halves (odd tail) run predicated with ex=0; all lanes shfl.
__global__ void __launch_bounds__(256)
k_aggr(const float* __restrict__ ea, const float* __restrict__ We,
       const float* __restrict__ att, float* __restrict__ out) {
    __shared__ float sWe[DEDGE * DOUT];
    __shared__ float sAtt[DOUT];
    for (int i = threadIdx.x; i < DEDGE * DOUT; i += 256) sWe[i] = We[i];
    if (threadIdx.x < DOUT) sAtt[threadIdx.x] = att[threadIdx.x];
    __syncthreads();

    int dst  = (int)((blockIdx.x * blockDim.x + threadIdx.x) >> 5);
    int lane = threadIdx.x & 31;
    int h    = lane >> 4;     // half: 0 or 1
    int c    = lane & 15;     // float4 chunk (dims 4c..4c+3)
    if (dst >= NN) return;

    const float4* sWe4 = (const float4*)sWe;
    float4 w[DEDGE];
#pragma unroll
    for (int k = 0; k < DEDGE; k++) w[k] = sWe4[k * 16 + c];
    float4 at4 = ((const float4*)sAtt)[c];

    float4 xrv = ((const float4*)g_xr)[(size_t)dst * 16 + c];

    int start = g_off[dst];
    int deg   = g_cnt[dst];

    float4 acc = make_float4(0.f, 0.f, 0.f, 0.f);
    float den = 0.f;
    float attr_sum = 0.f;   // lanes c<11 of each half

    for (int j = 0; j < deg; j += 2) {
        int  jj    = j + h;
        bool valid = jj < deg;
        int  idx   = start + (valid ? jj : 0);

        int2 es = __ldg(&g_csr[idx]);
        float av = (c < DEDGE) ? __ldg(&ea[(size_t)es.x * DEDGE + c]) : 0.f;
        float4 xlv = ((const float4*)g_xl)[(size_t)es.y * 16 + c];

        float4 e4 = make_float4(0.f, 0.f, 0.f, 0.f);
#pragma unroll
        for (int k = 0; k < DEDGE; k++) {
            float ak = __shfl_sync(FULL, av, k, 16);   // per-half broadcast
            e4.x = fmaf(ak, w[k].x, e4.x);
            e4.y = fmaf(ak, w[k].y, e4.y);
            e4.z = fmaf(ak, w[k].z, e4.z);
            e4.w = fmaf(ak, w[k].w, e4.w);
        }

        float m0 = xlv.x + xrv.x + e4.x;  m0 = (m0 >= 0.f) ? m0 : 0.2f * m0;
        float m1 = xlv.y + xrv.y + e4.y;  m1 = (m1 >= 0.f) ? m1 : 0.2f * m1;
        float m2 = xlv.z + xrv.z + e4.z;  m2 = (m2 >= 0.f) ? m2 : 0.2f * m2;
        float m3 = xlv.w + xrv.w + e4.w;  m3 = (m3 >= 0.f) ? m3 : 0.2f * m3;
        float v = fmaf(m0, at4.x, fmaf(m1, at4.y, fmaf(m2, at4.z, m3 * at4.w)));
#pragma unroll
        for (int o = 8; o > 0; o >>= 1)
            v += __shfl_xor_sync(FULL, v, o, 16);      // per-half reduce

        float ex = valid ? __expf(v) : 0.f;
        den += ex;
        attr_sum += valid ? av : 0.f;
        acc.x = fmaf(ex, xlv.x, acc.x);
        acc.y = fmaf(ex, xlv.y, acc.y);
        acc.z = fmaf(ex, xlv.z, acc.z);
        acc.w = fmaf(ex, xlv.w, acc.w);
    }

    // --- merge the two halves (both end up with identical totals) ---
    den      += __shfl_xor_sync(FULL, den, 16);
    attr_sum += __shfl_xor_sync(FULL, attr_sum, 16);
    acc.x    += __shfl_xor_sync(FULL, acc.x, 16);
    acc.y    += __shfl_xor_sync(FULL, acc.y, 16);
    acc.z    += __shfl_xor_sync(FULL, acc.z, 16);
    acc.w    += __shfl_xor_sync(FULL, acc.w, 16);

    // --- self-loop: attr = mean of incoming attrs (identical in both halves) --
    {
        float inv = 1.0f / fmaxf((float)deg, 1.0f);
        float av = attr_sum * inv;  // lanes c<11 hold per-dim means

        float4 e4 = make_float4(0.f, 0.f, 0.f, 0.f);
#pragma unroll
        for (int k = 0; k < DEDGE; k++) {
            float ak = __shfl_sync(FULL, av, k, 16);
            e4.x = fmaf(ak, w[k].x, e4.x);
            e4.y = fmaf(ak, w[k].y, e4.y);
            e4.z = fmaf(ak, w[k].z, e4.z);
            e4.w = fmaf(ak, w[k].w, e4.w);
        }

        float4 xlv = ((const float4*)g_xl)[(size_t)dst * 16 + c];
        float m0 = xlv.x + xrv.x + e4.x;  m0 = (m0 >= 0.f) ? m0 : 0.2f * m0;
        float m1 = xlv.y + xrv.y + e4.y;  m1 = (m1 >= 0.f) ? m1 : 0.2f * m1;
        float m2 = xlv.z + xrv.z + e4.z;  m2 = (m2 >= 0.f) ? m2 : 0.2f * m2;
        float m3 = xlv.w + xrv.w + e4.w;  m3 = (m3 >= 0.f) ? m3 : 0.2f * m3;
        float v = fmaf(m0, at4.x, fmaf(m1, at4.y, fmaf(m2, at4.z, m3 * at4.w)));
#pragma unroll
        for (int o = 8; o > 0; o >>= 1)
            v += __shfl_xor_sync(FULL, v, o, 16);

        float ex = __expf(v);
        den += ex;
        acc.x = fmaf(ex, xlv.x, acc.x);
        acc.y = fmaf(ex, xlv.y, acc.y);
        acc.z = fmaf(ex, xlv.z, acc.z);
        acc.w = fmaf(ex, xlv.w, acc.w);
    }

    if (h == 0) {
        float inv_den = 1.0f / den;
        ((float4*)out)[(size_t)dst * 16 + c] =
            make_float4(acc.x * inv_den, acc.y * inv_den,
                        acc.z * inv_den, acc.w * inv_den);
    }
}

// ---------------- launch -----------------------------------------------------
extern "C" void kernel_launch(void* const* d_in, const int* in_sizes, int n_in,
                              void* d_out, int out_size) {
    const float* x   = (const float*)d_in[0];
    const int*   ei  = (const int*)  d_in[1];
    const float* ea  = (const float*)d_in[2];
    const float* Wl  = (const float*)d_in[3];
    const float* Wr  = (const float*)d_in[4];
    const float* We  = (const float*)d_in[5];
    const float* att = (const float*)d_in[6];
    float* out = (float*)d_out;

    cudaFuncSetAttribute(k_gemm, cudaFuncAttributeMaxDynamicSharedMemorySize,
                         SM_TOT_F * 4);

    k_zero <<<(NN + 255) / 256, 256>>>();
    k_count<<<(EE + 255) / 256, 256>>>(ei);
    k_scan <<<1, 1024>>>();
    k_fill <<<(EE + 255) / 256, 256>>>(ei);
    int nblk = (NN + TILE_M - 1) / TILE_M;
    k_gemm <<<nblk, 256, SM_TOT_F * 4>>>(x, Wl, 1);
    k_gemm <<<nblk, 256, SM_TOT_F * 4>>>(x, Wr, 0);
    k_aggr <<<(NN * 32 + 255) / 256, 256>>>(ea, We, att, out);
}

// round 15
// speedup vs baseline: 1.3857x; 1.3857x over previous
#include <cuda_runtime.h>
#include <cstdint>

#define NN     100000
#define EE     1000000
#define DIN    128
#define DOUT   64
#define DEDGE  11
#define ET     (EE + NN)
#define FULL   0xFFFFFFFFu

// ---------------- scratch (device globals) ----------------------------------
__device__ float g_xl[NN * DOUT];          // x @ W_l   (25.6 MB)
__device__ float g_xr[NN * DOUT];          // x @ W_r   (25.6 MB)
__device__ int   g_cnt[NN];                // in-degree
__device__ int   g_off[NN];                // CSR offsets (exclusive scan)
__device__ int   g_cur[NN];                // fill cursors
__device__ int2  g_csr[EE];                // (edge_id, src) grouped by dst

// ---------------- 0: zero counters ------------------------------------------
__global__ void k_zero() {
    int i = blockIdx.x * blockDim.x + threadIdx.x;
    if (i < NN) g_cnt[i] = 0;
}

// ---------------- 1: in-degree histogram -------------------------------------
__global__ void k_count(const int* __restrict__ ei) {
    int e = blockIdx.x * blockDim.x + threadIdx.x;
    if (e >= EE) return;
    atomicAdd(&g_cnt[__ldg(&ei[EE + e])], 1);
}

// ---------------- 2: exclusive prefix scan (single block) --------------------
__global__ void k_scan() {
    __shared__ int warp_sums[32];
    __shared__ int s_carry, s_total;
    int tid = threadIdx.x;
    int lane = tid & 31, wid = tid >> 5;
    if (tid == 0) s_carry = 0;
    __syncthreads();
    for (int base = 0; base < NN; base += 1024) {
        int i = base + tid;
        int v = (i < NN) ? g_cnt[i] : 0;
        int incl = v;
#pragma unroll
        for (int o = 1; o < 32; o <<= 1) {
            int t = __shfl_up_sync(FULL, incl, o);
            if (lane >= o) incl += t;
        }
        if (lane == 31) warp_sums[wid] = incl;
        __syncthreads();
        if (wid == 0) {
            int ws = warp_sums[lane];
            int wincl = ws;
#pragma unroll
            for (int o = 1; o < 32; o <<= 1) {
                int t = __shfl_up_sync(FULL, wincl, o);
                if (lane >= o) wincl += t;
            }
            warp_sums[lane] = wincl - ws;       // exclusive warp offset
            if (lane == 31) s_total = wincl;    // chunk total
        }
        __syncthreads();
        int excl = incl - v + warp_sums[wid] + s_carry;
        if (i < NN) { g_off[i] = excl; g_cur[i] = excl; }
        __syncthreads();
        if (tid == 0) s_carry += s_total;
        __syncthreads();
    }
}

// ---------------- 3: CSR fill -------------------------------------------------
__global__ void k_fill(const int* __restrict__ ei) {
    int e = blockIdx.x * blockDim.x + threadIdx.x;
    if (e >= EE) return;
    int src = __ldg(&ei[e]);
    int dst = __ldg(&ei[EE + e]);
    int pos = atomicAdd(&g_cur[dst], 1);
    g_csr[pos] = make_int2(e, src);
}

// ---------------- 4: tensor-core GEMM (3xTF32), W pre-split in smem ----------
#define SXS   132
#define SWS   72
#define SM_X    0
#define SM_WH  (SM_X + 64 * SXS)            // 8448
#define SM_WLO (SM_WH + 128 * SWS)          // 17664
#define SM_TOT_F (SM_WLO + 128 * SWS)       // 26880 floats = 107520 B
#define TILE_M 64

__device__ __forceinline__ unsigned f2tf(float f) {
    unsigned u;
    asm("cvt.rna.tf32.f32 %0, %1;" : "=r"(u) : "f"(f));
    return u;
}
__device__ __forceinline__ void mma_tf32(float* d, unsigned a0, unsigned a1,
                                         unsigned a2, unsigned a3,
                                         unsigned b0, unsigned b1) {
    asm volatile(
        "mma.sync.aligned.m16n8k8.row.col.f32.tf32.tf32.f32 "
        "{%0,%1,%2,%3}, {%4,%5,%6,%7}, {%8,%9}, {%0,%1,%2,%3};"
        : "+f"(d[0]), "+f"(d[1]), "+f"(d[2]), "+f"(d[3])
        : "r"(a0), "r"(a1), "r"(a2), "r"(a3), "r"(b0), "r"(b1));
}

__global__ void __launch_bounds__(256, 2)
k_gemm(const float* __restrict__ x, const float* __restrict__ W, int is_l) {
    extern __shared__ float sm[];
    float* sx = sm + SM_X;
    float* gout = is_l ? g_xl : g_xr;   // device-side symbol reference (valid)

    int tid  = threadIdx.x;
    int warp = tid >> 5;
    int lane = tid & 31;
    int grp  = lane >> 2;
    int ctid = lane & 3;

    // --- fill W as tf32 hi/lo (once per block, float4-wide) ---
    for (int i = tid; i < (DIN * DOUT) / 4; i += 256) {
        int k = i >> 4, n4 = (i & 15) * 4;
        float4 v = __ldg((const float4*)W + i);
        float4 hi, lo;
        hi.x = __uint_as_float(f2tf(v.x)); lo.x = __uint_as_float(f2tf(v.x - hi.x));
        hi.y = __uint_as_float(f2tf(v.y)); lo.y = __uint_as_float(f2tf(v.y - hi.y));
        hi.z = __uint_as_float(f2tf(v.z)); lo.z = __uint_as_float(f2tf(v.z - hi.z));
        hi.w = __uint_as_float(f2tf(v.w)); lo.w = __uint_as_float(f2tf(v.w - hi.w));
        *(float4*)&sm[SM_WH  + k * SWS + n4] = hi;
        *(float4*)&sm[SM_WLO + k * SWS + n4] = lo;
    }

    // --- load x tile 64 x 128 (zero-pad OOB rows) ---
    int row0 = blockIdx.x * TILE_M;
    {
        const float4* xg = (const float4*)x;
        for (int i = tid; i < TILE_M * 32; i += 256) {
            int r = i >> 5, c4 = i & 31;
            float4 v = make_float4(0.f, 0.f, 0.f, 0.f);
            if (row0 + r < NN) v = xg[(size_t)(row0 + r) * 32 + c4];
            *(float4*)&sx[r * SXS + c4 * 4] = v;
        }
    }
    __syncthreads();

    int rb = (warp & 3) * 16;      // row slab within tile
    int nh = (warp >> 2) * 32;     // n-half base column

    float d[4][4];
#pragma unroll
    for (int t = 0; t < 4; t++)
#pragma unroll
        for (int q = 0; q < 4; q++) d[t][q] = 0.f;

#pragma unroll 1
    for (int k0 = 0; k0 < DIN; k0 += 8) {
        // B fragments: pure LDS, already tf32
        unsigned bh[4][2], bl[4][2];
        const float* ph0 = sm + SM_WH  + (k0 + ctid) * SWS + nh + grp;
        const float* ph1 = sm + SM_WH  + (k0 + ctid + 4) * SWS + nh + grp;
        const float* pl0 = sm + SM_WLO + (k0 + ctid) * SWS + nh + grp;
        const float* pl1 = sm + SM_WLO + (k0 + ctid + 4) * SWS + nh + grp;
#pragma unroll
        for (int t = 0; t < 4; t++) {
            bh[t][0] = __float_as_uint(ph0[8 * t]);
            bh[t][1] = __float_as_uint(ph1[8 * t]);
            bl[t][0] = __float_as_uint(pl0[8 * t]);
            bl[t][1] = __float_as_uint(pl1[8 * t]);
        }
        // A fragment: cvt on the fly (only 4 values)
        float f0 = sx[(rb + grp)     * SXS + k0 + ctid];
        float f1 = sx[(rb + grp + 8) * SXS + k0 + ctid];
        float f2 = sx[(rb + grp)     * SXS + k0 + ctid + 4];
        float f3 = sx[(rb + grp + 8) * SXS + k0 + ctid + 4];
        unsigned a0 = f2tf(f0), a1 = f2tf(f1), a2 = f2tf(f2), a3 = f2tf(f3);
        unsigned l0 = f2tf(f0 - __uint_as_float(a0));
        unsigned l1 = f2tf(f1 - __uint_as_float(a1));
        unsigned l2 = f2tf(f2 - __uint_as_float(a2));
        unsigned l3 = f2tf(f3 - __uint_as_float(a3));
#pragma unroll
        for (int t = 0; t < 4; t++) {
            mma_tf32(d[t], a0, a1, a2, a3, bh[t][0], bh[t][1]);
            mma_tf32(d[t], l0, l1, l2, l3, bh[t][0], bh[t][1]);
            mma_tf32(d[t], a0, a1, a2, a3, bl[t][0], bl[t][1]);
        }
    }

    {
        int r0 = row0 + rb + grp;
        int r1 = r0 + 8;
#pragma unroll
        for (int t = 0; t < 4; t++) {
            int col = nh + 8 * t + 2 * ctid;
            if (r0 < NN)
                *(float2*)&gout[(size_t)r0 * DOUT + col] =
                    make_float2(d[t][0], d[t][1]);
            if (r1 < NN)
                *(float2*)&gout[(size_t)r1 * DOUT + col] =
                    make_float2(d[t][2], d[t][3]);
        }
    }
}

// ---------------- 5: CSR aggregation (R12 shape + We-hoist + dual reduce) ----
// One warp per destination, unroll-2. We column in registers (float2[11],
// 22 regs — kills 11 LDS/edge). Pair reduce: 2 shfls fold v0/v1 into halves,
// 4-shfl width-16 butterfly, 1 exchange => 7 shfls/pair (was 10), 1 exp/lane.
__global__ void __launch_bounds__(256)
k_aggr(const float* __restrict__ ea, const float* __restrict__ We,
       const float* __restrict__ att, float* __restrict__ out) {
    __shared__ float sWe[DEDGE * DOUT];
    __shared__ float sAtt[DOUT];
    for (int i = threadIdx.x; i < DEDGE * DOUT; i += 256) sWe[i] = We[i];
    if (threadIdx.x < DOUT) sAtt[threadIdx.x] = att[threadIdx.x];
    __syncthreads();

    int dst  = (int)((blockIdx.x * blockDim.x + threadIdx.x) >> 5);
    int lane = threadIdx.x & 31;
    if (dst >= NN) return;

    const float2* sWe2  = (const float2*)sWe;
    const float2* sAtt2 = (const float2*)sAtt;
    float2 at = sAtt2[lane];

    // hoist this lane's We column (loop-invariant across edges)
    float2 w[DEDGE];
#pragma unroll
    for (int k = 0; k < DEDGE; k++) w[k] = sWe2[k * 32 + lane];

    float2 xrv = ((const float2*)g_xr)[(size_t)dst * 32 + lane];

    int start = g_off[dst];
    int deg   = g_cnt[dst];

    float2 acc = make_float2(0.f, 0.f);
    float den = 0.f;
    float attr_sum = 0.f;   // lanes 0..10 hold per-dim attr sums
    bool lo16 = lane < 16;

    int j = 0;
    for (; j + 2 <= deg; j += 2) {
        int2 es0 = __ldg(&g_csr[start + j]);
        int2 es1 = __ldg(&g_csr[start + j + 1]);
        float av0 = (lane < DEDGE) ? __ldg(&ea[(size_t)es0.x * DEDGE + lane]) : 0.f;
        float av1 = (lane < DEDGE) ? __ldg(&ea[(size_t)es1.x * DEDGE + lane]) : 0.f;
        float2 xlv0 = ((const float2*)g_xl)[(size_t)es0.y * 32 + lane];
        float2 xlv1 = ((const float2*)g_xl)[(size_t)es1.y * 32 + lane];
        attr_sum += av0 + av1;

        float e00 = 0.f, e01 = 0.f, e10 = 0.f, e11 = 0.f;
#pragma unroll
        for (int k = 0; k < DEDGE; k++) {
            float ak0 = __shfl_sync(FULL, av0, k);
            float ak1 = __shfl_sync(FULL, av1, k);
            e00 = fmaf(ak0, w[k].x, e00);
            e01 = fmaf(ak0, w[k].y, e01);
            e10 = fmaf(ak1, w[k].x, e10);
            e11 = fmaf(ak1, w[k].y, e11);
        }

        float m00 = xlv0.x + xrv.x + e00;  m00 = (m00 >= 0.f) ? m00 : 0.2f * m00;
        float m01 = xlv0.y + xrv.y + e01;  m01 = (m01 >= 0.f) ? m01 : 0.2f * m01;
        float m10 = xlv1.x + xrv.x + e10;  m10 = (m10 >= 0.f) ? m10 : 0.2f * m10;
        float m11 = xlv1.y + xrv.y + e11;  m11 = (m11 >= 0.f) ? m11 : 0.2f * m11;
        float v0 = m00 * at.x + m01 * at.y;
        float v1 = m10 * at.x + m11 * at.y;

        // dual reduce: fold the two 32-lane sums into the two 16-lane halves
        float t0 = __shfl_xor_sync(FULL, v0, 16);
        float t1 = __shfl_xor_sync(FULL, v1, 16);
        float c  = lo16 ? (v0 + t0) : (v1 + t1);
#pragma unroll
        for (int o = 8; o > 0; o >>= 1)
            c += __shfl_xor_sync(FULL, c, o, 16);
        // lanes<16: S0, lanes>=16: S1
        float exm = __expf(c);
        float exo = __shfl_xor_sync(FULL, exm, 16);
        float ex0 = lo16 ? exm : exo;
        float ex1 = lo16 ? exo : exm;

        den += ex0 + ex1;
        acc.x = fmaf(ex0, xlv0.x, fmaf(ex1, xlv1.x, acc.x));
        acc.y = fmaf(ex0, xlv0.y, fmaf(ex1, xlv1.y, acc.y));
    }
    if (j < deg) {
        int2 es = __ldg(&g_csr[start + j]);
        float av = (lane < DEDGE) ? __ldg(&ea[(size_t)es.x * DEDGE + lane]) : 0.f;
        float2 xlv = ((const float2*)g_xl)[(size_t)es.y * 32 + lane];
        attr_sum += av;
        float e0 = 0.f, e1 = 0.f;
#pragma unroll
        for (int k = 0; k < DEDGE; k++) {
            float ak = __shfl_sync(FULL, av, k);
            e0 = fmaf(ak, w[k].x, e0);
            e1 = fmaf(ak, w[k].y, e1);
        }
        float m0 = xlv.x + xrv.x + e0;  m0 = (m0 >= 0.f) ? m0 : 0.2f * m0;
        float m1 = xlv.y + xrv.y + e1;  m1 = (m1 >= 0.f) ? m1 : 0.2f * m1;
        float v = m0 * at.x + m1 * at.y;
#pragma unroll
        for (int o = 16; o > 0; o >>= 1)
            v += __shfl_xor_sync(FULL, v, o);
        float ex = __expf(v);
        den += ex;
        acc.x = fmaf(ex, xlv.x, acc.x);
        acc.y = fmaf(ex, xlv.y, acc.y);
    }

    // --- self-loop: attr = mean of incoming attrs ---
    {
        float inv = 1.0f / fmaxf((float)deg, 1.0f);
        float av = attr_sum * inv;  // valid on lanes 0..10

        float e0 = 0.f, e1 = 0.f;
#pragma unroll
        for (int k = 0; k < DEDGE; k++) {
            float ak = __shfl_sync(FULL, av, k);
            e0 = fmaf(ak, w[k].x, e0);
            e1 = fmaf(ak, w[k].y, e1);
        }

        float2 xlv = ((const float2*)g_xl)[(size_t)dst * 32 + lane];
        float m0 = xlv.x + xrv.x + e0;  m0 = (m0 >= 0.f) ? m0 : 0.2f * m0;
        float m1 = xlv.y + xrv.y + e1;  m1 = (m1 >= 0.f) ? m1 : 0.2f * m1;
        float v = m0 * at.x + m1 * at.y;
#pragma unroll
        for (int o = 16; o > 0; o >>= 1)
            v += __shfl_xor_sync(FULL, v, o);

        float ex = __expf(v);
        den += ex;
        acc.x = fmaf(ex, xlv.x, acc.x);
        acc.y = fmaf(ex, xlv.y, acc.y);
    }

    float inv_den = 1.0f / den;
    ((float2*)out)[(size_t)dst * 32 + lane] =
        make_float2(acc.x * inv_den, acc.y * inv_den);
}

// ---------------- launch -----------------------------------------------------
extern "C" void kernel_launch(void* const* d_in, const int* in_sizes, int n_in,
                              void* d_out, int out_size) {
    const float* x   = (const float*)d_in[0];
    const int*   ei  = (const int*)  d_in[1];
    const float* ea  = (const float*)d_in[2];
    const float* Wl  = (const float*)d_in[3];
    const float* Wr  = (const float*)d_in[4];
    const float* We  = (const float*)d_in[5];
    const float* att = (const float*)d_in[6];
    float* out = (float*)d_out;

    cudaFuncSetAttribute(k_gemm, cudaFuncAttributeMaxDynamicSharedMemorySize,
                         SM_TOT_F * 4);

    k_zero <<<(NN + 255) / 256, 256>>>();
    k_count<<<(EE + 255) / 256, 256>>>(ei);
    k_scan <<<1, 1024>>>();
    k_fill <<<(EE + 255) / 256, 256>>>(ei);
    int nblk = (NN + TILE_M - 1) / TILE_M;
    k_gemm <<<nblk, 256, SM_TOT_F * 4>>>(x, Wl, 1);
    k_gemm <<<nblk, 256, SM_TOT_F * 4>>>(x, Wr, 0);
    k_aggr <<<(NN * 32 + 255) / 256, 256>>>(ea, We, att, out);
}